// round 1
// baseline (speedup 1.0000x reference)
#include <cuda_runtime.h>
#include <cuda_bf16.h>

// FilterLayer: out = irfft(rfft(x, ortho) * W, ortho) + x  over last dim (L=12)
// == per-node circulant matvec: out[t] = sum_j h'[n][(t-j) mod 12] * x[j]
// with h'[0] including the +1 residual.

#define SEQ 12
#define NODES 207
#define NFREQ 7   // SEQ/2+1

// Persistent scratch for the per-node circulant taps (allocation-free rule).
__device__ float g_H[NODES * SEQ];

// Exact cos/sin(m*pi/6) tables, m = 0..11
__device__ __constant__ double c_COS[12] = {
    1.0,  0.8660254037844387,  0.5,  0.0, -0.5, -0.8660254037844387,
   -1.0, -0.8660254037844387, -0.5,  0.0,  0.5,  0.8660254037844387
};
__device__ __constant__ double c_SIN[12] = {
    0.0,  0.5,  0.8660254037844387,  1.0,  0.8660254037844387,  0.5,
    0.0, -0.5, -0.8660254037844387, -1.0, -0.8660254037844387, -0.5
};

// Build H[n][d]: one block per node, 12 threads.
__global__ void build_taps_kernel(const float* __restrict__ w /*[207][7][2]*/) {
    int n = blockIdx.x;
    int d = threadIdx.x;
    if (d >= SEQ) return;
    const float* wn = w + n * (NFREQ * 2);

    double acc = (double)wn[0];                                 // Re(W0)
    acc += ((d & 1) ? -1.0 : 1.0) * (double)wn[2 * 6];          // (-1)^d * Re(W6)
    #pragma unroll
    for (int k = 1; k <= 5; k++) {
        int m = (k * d) % 12;
        acc += 2.0 * ((double)wn[2 * k] * c_COS[m] - (double)wn[2 * k + 1] * c_SIN[m]);
    }
    float h = (float)(acc / 12.0);
    if (d == 0) h += 1.0f;   // fold residual identity into the d=0 tap
    g_H[n * SEQ + d] = h;
}

__global__ void __launch_bounds__(256) filter_apply_kernel(
    const float4* __restrict__ x, float4* __restrict__ out, int nrows)
{
    int r = blockIdx.x * blockDim.x + threadIdx.x;
    if (r >= nrows) return;
    int n = r % NODES;

    // Load one row of 12 floats (48B, float4-aligned since 12*4=48, 48%16==0)
    float4 a = __ldg(x + (size_t)r * 3 + 0);
    float4 b = __ldg(x + (size_t)r * 3 + 1);
    float4 c = __ldg(x + (size_t)r * 3 + 2);
    float xv[SEQ] = { a.x, a.y, a.z, a.w,  b.x, b.y, b.z, b.w,  c.x, c.y, c.z, c.w };

    // Load the 12 taps for this node (48B, float4-aligned)
    const float4* Hv = reinterpret_cast<const float4*>(g_H + n * SEQ);
    float4 h0 = __ldg(Hv + 0);
    float4 h1 = __ldg(Hv + 1);
    float4 h2 = __ldg(Hv + 2);
    float h[SEQ] = { h0.x, h0.y, h0.z, h0.w,  h1.x, h1.y, h1.z, h1.w,
                     h2.x, h2.y, h2.z, h2.w };

    float y[SEQ];
    #pragma unroll
    for (int t = 0; t < SEQ; t++) {
        float s = 0.0f;
        #pragma unroll
        for (int j = 0; j < SEQ; j++) {
            s = fmaf(h[(t - j + SEQ) % SEQ], xv[j], s);   // compile-time index
        }
        y[t] = s;
    }

    float4 o0 = make_float4(y[0], y[1], y[2],  y[3]);
    float4 o1 = make_float4(y[4], y[5], y[6],  y[7]);
    float4 o2 = make_float4(y[8], y[9], y[10], y[11]);
    out[(size_t)r * 3 + 0] = o0;
    out[(size_t)r * 3 + 1] = o1;
    out[(size_t)r * 3 + 2] = o2;
}

extern "C" void kernel_launch(void* const* d_in, const int* in_sizes, int n_in,
                              void* d_out, int out_size) {
    const float* x = (const float*)d_in[0];        // [1024,32,207,12] fp32
    const float* w = (const float*)d_in[1];        // [1,207,7,2] fp32
    float* out = (float*)d_out;

    // 1) build per-node circulant taps (tiny)
    build_taps_kernel<<<NODES, SEQ>>>(w);

    // 2) apply: one thread per length-12 row
    int nrows = out_size / SEQ;                    // 1024*32*207 = 6,782,976
    int threads = 256;
    int blocks = (nrows + threads - 1) / threads;
    filter_apply_kernel<<<blocks, threads>>>(
        reinterpret_cast<const float4*>(x),
        reinterpret_cast<float4*>(out),
        nrows);
}